// round 12
// baseline (speedup 1.0000x reference)
#include <cuda_runtime.h>
#include <math.h>

#define BB 4
#define NN 325
#define TT 288
#define FF 64
#define HH 8
#define LL 24
#define NTOP 5
#define BN (BB*NN)

#define OFF_DELAY (BB*NN*TT*FF)                 // 23961600
#define OFF_TMP   (OFF_DELAY + BN*HH*NTOP)      // +52000
#define OFF_ADJ2  (OFF_TMP + BN*HH*NTOP)        // +52000

// ---------------- scratch (static device globals; no runtime alloc) -------
__device__ float g_s[BN*TT];        // s[b,n,t]
__device__ float g_sm[BN*TT];       // sm[b,n,t] = adj2 @ s
__device__ float g_sq[BN];
__device__ float g_sk[BN];
__device__ float g_gw[128];
__device__ float g_coef[5][FF];     // poly coeffs a1,a2,a4,a6,a8
__device__ float g_xsafe;
__device__ float g_D[4];            // D[sigma][tau] = W_sigma . R_tau
__device__ __align__(16) float g_Wqp[HH*768];   // permuted Wq: [h][p*64+f]
__device__ __align__(16) float g_Wkp[HH*768];
__device__ float g_wtop[BN*HH*NTOP];
__device__ int   g_dtop[BN*HH*NTOP];
__device__ int   g_nopsink;

// ---------------- K0: weight precompute + conv-weight permute -------------
__global__ __launch_bounds__(256) void k0(
    const float* __restrict__ Wout_map, const float* __restrict__ gWg,
    const float* __restrict__ gWout, const float* __restrict__ gQ2,
    const float* __restrict__ gK2, const float* __restrict__ gWa,
    const float* __restrict__ Wq, const float* __restrict__ Wk)
{
    int tid = threadIdx.x;   // 256 threads
    __shared__ float ws[64], wp[64], wm[64];
    __shared__ float gsh[128];
    __shared__ float Pp[128], Pm[128], Rp[128], Rm[128];
    __shared__ float Wp[128], Wm[128];

    for (int i = tid; i < HH*768; i += 256) {
        int h = i / 768, r = i % 768, p = r >> 6, f = r & 63;
        g_Wqp[i] = Wq[h*768 + f*12 + p];
        g_Wkp[i] = Wk[h*768 + f*12 + p];
    }

    if (tid < 64) {
        float a = 0.f;
#pragma unroll
        for (int c = 0; c < 8; c++) a += Wout_map[tid*8 + c];
        ws[tid] = a;
        wp[tid] = fmaxf(a, 0.f);
        wm[tid] = fmaxf(-a, 0.f);
    }
    __syncthreads();
    if (tid < 128) {
        float a = 0.f;
        for (int f = 0; f < 64; f++) a += ws[f] * gWg[f*128 + tid];
        g_gw[tid] = a; gsh[tid] = a;
        float pp = 0.f, pm = 0.f, rp = 0.f, rm = 0.f;
        for (int f = 0; f < 64; f++) {
            float q = gQ2[tid*64 + f], k = gK2[tid*64 + f];
            pp += q * wp[f]; pm += q * wm[f];
            rp += k * wp[f]; rm += k * wm[f];
        }
        Pp[tid] = pp; Pm[tid] = pm; Rp[tid] = rp; Rm[tid] = rm;
    }
    __syncthreads();
    if (tid == 0) {
        float m = 0.f;
        for (int h = 0; h < 128; h++) m = fmaxf(m, fabsf(gsh[h]));
        g_xsafe = 0.68f / fmaxf(m, 1e-30f);
    }
    if (tid < 128) {
        float a = 0.f, b = 0.f;
        for (int h = 0; h < 128; h++) {
            float w = gWa[h*128 + tid];
            a += Pp[h] * w; b += Pm[h] * w;
        }
        Wp[tid] = a; Wm[tid] = b;
    }
    if (tid < 64) {
        float c1=0.f,c2=0.f,c4=0.f,c6=0.f,c8=0.f;
        for (int h = 0; h < 128; h++) {
            float g = gsh[h], w = gWout[h*64 + tid];
            float g2 = g*g, g4 = g2*g2;
            c1 += g*w; c2 += g2*w; c4 += g4*w; c6 += g4*g2*w; c8 += g4*g4*w;
        }
        const float C = 0.3989422804014327f;  // 1/sqrt(2*pi)
        g_coef[0][tid] =  0.5f*c1;
        g_coef[1][tid] =  C*c2;
        g_coef[2][tid] = -C*c4*(1.f/6.f);
        g_coef[3][tid] =  C*c6*(1.f/40.f);
        g_coef[4][tid] = -C*c8*(1.f/336.f);
    }
    __syncthreads();
    if (tid < 4) {
        int sg = tid >> 1, tu = tid & 1;
        const float* Wv = sg ? Wm : Wp;
        const float* Rv = tu ? Rm : Rp;
        float d = 0.f;
        for (int j = 0; j < 128; j++) d += Wv[j] * Rv[j];
        g_D[tid] = d;
    }
}

// ---------------- nop fillers (so k1a lands at profile idx 3) -------------
__global__ void knop1() { if (threadIdx.x == 1024) g_nopsink = 1; }
__global__ void knop2() { if (threadIdx.x == 1024) g_nopsink = 2; }

// ---------------- K1a: q/k projection + corr + topk + softmax -------------
// 256 threads = 8 warps. Warps 0-3: Q patches 6w..6w+5; warps 4-7: K.
// 8 weight-LDS per 6 data-LDG (halves smem crossbar traffic vs 3-patch).
__global__ __launch_bounds__(256, 2) void k1a(
    const float* __restrict__ Qin, const float* __restrict__ Kin,
    float* __restrict__ out)
{
    __shared__ __align__(16) float4 Wq4[HH*192];   // 24 KB
    __shared__ __align__(16) float4 Wk4[HH*192];   // 24 KB
    __shared__ float qh[192], kh[192], corr[192];

    int bn   = blockIdx.x;
    int tid  = threadIdx.x;
    int w    = tid >> 5, lane = tid & 31;

    const float4* wq_g = reinterpret_cast<const float4*>(g_Wqp);
    const float4* wk_g = reinterpret_cast<const float4*>(g_Wkp);
    for (int i = tid; i < HH*192; i += 256) { Wq4[i] = wq_g[i]; Wk4[i] = wk_g[i]; }
    __syncthreads();

    {
        bool isQ = (w < 4);
        int l0 = (isQ ? w : (w - 4)) * 6;
        const float4* Db = reinterpret_cast<const float4*>(isQ ? Qin : Kin)
                         + (size_t)bn * (TT*FF/4);
        const float4* Wt = isQ ? Wq4 : Wk4;
        float* dst = isQ ? qh : kh;

        float acc[6][8];
#pragma unroll
        for (int j = 0; j < 6; j++)
#pragma unroll
            for (int h = 0; h < 8; h++) acc[j][h] = 0.f;

#pragma unroll
        for (int it = 0; it < 6; it++) {
            float4 d[6];
#pragma unroll
            for (int j = 0; j < 6; j++)
                d[j] = Db[(l0 + j)*192 + it*32 + lane];
#pragma unroll
            for (int h = 0; h < 8; h++) {
                float4 wv = Wt[h*192 + it*32 + lane];
#pragma unroll
                for (int j = 0; j < 6; j++)
                    acc[j][h] += d[j].x*wv.x + d[j].y*wv.y + d[j].z*wv.z + d[j].w*wv.w;
            }
        }
#pragma unroll
        for (int j = 0; j < 6; j++)
#pragma unroll
            for (int h = 0; h < 8; h++) {
                float a = acc[j][h];
#pragma unroll
                for (int o = 16; o; o >>= 1) a += __shfl_xor_sync(0xffffffffu, a, o);
                if (lane == 0) dst[h*24 + l0 + j] = a;
            }
    }
    __syncthreads();

    // circular correlation: corr[h][d] = sum_m q[(m+d)%24]*k[m]
    if (tid < 192) {
        int h = tid / 24, d = tid % 24;
        float a = 0.f;
#pragma unroll
        for (int m = 0; m < 24; m++) {
            int i = m + d; if (i >= 24) i -= 24;
            a += qh[h*24 + i] * kh[h*24 + m];
        }
        corr[h*24 + d] = a;
    }
    __syncthreads();

    // top-5 per head (strict > keeps lowest index on ties, like lax.top_k)
    if (tid < 8) {
        int h = tid;
        float vals[24];
#pragma unroll
        for (int d = 0; d < 24; d++) vals[d] = corr[h*24 + d];
        float wv[5]; int dd[5];
#pragma unroll
        for (int i = 0; i < 5; i++) {
            float best = -1e30f; int bd = 0;
#pragma unroll
            for (int d = 0; d < 24; d++) if (vals[d] > best) { best = vals[d]; bd = d; }
            wv[i] = best; dd[i] = bd; vals[bd] = -1e30f;
        }
        float mx = wv[0], s = 0.f, e[5];
#pragma unroll
        for (int i = 0; i < 5; i++) { e[i] = expf(wv[i] - mx); s += e[i]; }
        float inv = 1.f / s;
#pragma unroll
        for (int i = 0; i < 5; i++) {
            float ww = e[i] * inv;
            g_wtop[(bn*8 + h)*5 + i] = ww;
            g_dtop[(bn*8 + h)*5 + i] = dd[i];
            out[OFF_DELAY + (bn*8 + h)*5 + i] = (float)(dd[i] * 12);
            out[OFF_TMP   + (bn*8 + h)*5 + i] = ww;
        }
    }
}

// ---------------- K1bc: fused v_small + delay aggregation (R4 staged) -----
__global__ __launch_bounds__(288) void k1bc(const float* __restrict__ Vin,
                                            const float* __restrict__ Wv,
                                            const float* __restrict__ gQ1,
                                            const float* __restrict__ gK1)
{
    __shared__ __align__(16) float Vs[TT*68];    // 78336 B (stride 17 float4)
    __shared__ float vs[TT*9];                   // 10368 B
    __shared__ __align__(16) float Wvs[8*68];    // 2176 B
    __shared__ float wt[40];
    __shared__ int   dt[40];
    __shared__ float red1[9], red2[9];

    int bn = blockIdx.x, tid = threadIdx.x;
    int warp = tid >> 5, lane = tid & 31;

    if (tid < 128) {
        int h = tid >> 4, c4 = tid & 15;
        reinterpret_cast<float4*>(Wvs)[h*17 + c4] =
            reinterpret_cast<const float4*>(Wv)[h*16 + c4];
    }
    if (tid < 40) { wt[tid] = g_wtop[bn*40 + tid]; dt[tid] = g_dtop[bn*40 + tid]; }

    {
        const float4* src = reinterpret_cast<const float4*>(Vin) + (size_t)bn * (TT*FF/4);
        float4* dst = reinterpret_cast<float4*>(Vs);
#pragma unroll
        for (int k = 0; k < 16; k++) {
            int idx = tid + k*288;
            float4 v = src[idx];
            int r = idx >> 4, c4 = idx & 15;
            dst[r*17 + c4] = v;
        }
    }
    __syncthreads();

    {
        int t = tid;
        float acc[8] = {0.f,0.f,0.f,0.f,0.f,0.f,0.f,0.f};
        const float4* vrow = reinterpret_cast<const float4*>(Vs) + t*17;
        const float4* wv4  = reinterpret_cast<const float4*>(Wvs);
#pragma unroll
        for (int f4 = 0; f4 < 16; f4++) {
            float4 v = vrow[f4];
#pragma unroll
            for (int h = 0; h < 8; h++) {
                float4 w = wv4[h*17 + f4];
                acc[h] += v.x*w.x + v.y*w.y + v.z*w.z + v.w*w.w;
            }
        }
#pragma unroll
        for (int h = 0; h < 8; h++) vs[t*9 + h] = acc[h];
    }
    __syncthreads();

    {
        int t = tid;
        float sv = 0.f;
#pragma unroll
        for (int h = 0; h < 8; h++)
#pragma unroll
            for (int i = 0; i < 5; i++) {
                int idx = dt[h*5 + i]*12 + t; if (idx >= 288) idx -= 288;
                sv += wt[h*5 + i] * vs[idx*9 + h];
            }
        sv *= 0.125f;
        g_s[bn*288 + t] = sv;
        float pq = sv * __ldg(gQ1 + t);
        float pk = sv * __ldg(gK1 + t);
#pragma unroll
        for (int o = 16; o; o >>= 1) {
            pq += __shfl_xor_sync(0xffffffffu, pq, o);
            pk += __shfl_xor_sync(0xffffffffu, pk, o);
        }
        if (lane == 0) { red1[warp] = pq; red2[warp] = pk; }
    }
    __syncthreads();
    if (tid == 0) {
        float a = 0.f, b2 = 0.f;
#pragma unroll
        for (int w2 = 0; w2 < 9; w2++) { a += red1[w2]; b2 += red2[w2]; }
        g_sq[bn] = a; g_sk[bn] = b2;
    }
}

// ---------------- K3: rank-2 attention logits + softmax * adj -> adj2 -----
__global__ __launch_bounds__(352) void k3(const float* __restrict__ adj,
                                          float* __restrict__ out)
{
    __shared__ float red[11];
    int n = blockIdx.x, b = blockIdx.y;
    int bn = b*NN + n;
    int tid = threadIdx.x, w = tid >> 5, lane = tid & 31;

    float sq = g_sq[bn];
    float c  = fabsf(sq);
    const float d0 = (sq < 0.f) ? g_D[2] : g_D[0];
    const float d1 = (sq < 0.f) ? g_D[3] : g_D[1];

    float x = -1e30f;
    if (tid < NN) {
        float sk = g_sk[b*NN + tid];
        x = c * fabsf(sk) * (sk < 0.f ? d1 : d0);
    }
    float mx = x;
#pragma unroll
    for (int o = 16; o; o >>= 1) mx = fmaxf(mx, __shfl_xor_sync(0xffffffffu, mx, o));
    if (lane == 0) red[w] = mx;
    __syncthreads();
    {
        float m2 = -1e30f;
#pragma unroll
        for (int i = 0; i < 11; i++) m2 = fmaxf(m2, red[i]);
        mx = m2;
    }
    __syncthreads();
    float e = (tid < NN) ? expf(x - mx) : 0.f;
    float s = e;
#pragma unroll
    for (int o = 16; o; o >>= 1) s += __shfl_xor_sync(0xffffffffu, s, o);
    if (lane == 0) red[w] = s;
    __syncthreads();
    {
        float s2 = 0.f;
#pragma unroll
        for (int i = 0; i < 11; i++) s2 += red[i];
        s = s2;
    }
    if (tid < NN)
        out[OFF_ADJ2 + (size_t)bn*NN + tid] = e * (1.f / s) * __ldg(adj + n*NN + tid);
}

// ---------------- K4: sm = adj2 @ s (8 rows/block, plain FMA, no asm) -----
__global__ __launch_bounds__(288) void k4(const float* __restrict__ adj2)
{
    int b = blockIdx.y, n0 = blockIdx.x * 8;
    int nrows = NN - n0; if (nrows > 8) nrows = 8;
    __shared__ __align__(16) float art[NN*8];    // transposed: art[m*8 + r]
    int tid = threadIdx.x;
    const float* src = adj2 + ((size_t)b*NN + n0)*NN;
    for (int i = tid; i < 8*NN; i += 288) {
        int r = i / NN, m = i - r*NN;
        art[m*8 + r] = (r < nrows) ? src[i] : 0.f;
    }
    __syncthreads();

    int t = tid;
    float a0=0.f,a1=0.f,a2=0.f,a3=0.f,a4=0.f,a5=0.f,a6=0.f,a7=0.f;
    const float* sb = g_s + (size_t)b*NN*TT;
#pragma unroll 10
    for (int m = 0; m < NN; m++) {
        float sv = sb[m*TT + t];
        a0 += art[m*8 + 0] * sv;
        a1 += art[m*8 + 1] * sv;
        a2 += art[m*8 + 2] * sv;
        a3 += art[m*8 + 3] * sv;
        a4 += art[m*8 + 4] * sv;
        a5 += art[m*8 + 5] * sv;
        a6 += art[m*8 + 6] * sv;
        a7 += art[m*8 + 7] * sv;
    }
    float accs[8] = {a0,a1,a2,a3,a4,a5,a6,a7};
#pragma unroll
    for (int r = 0; r < 8; r++)
        if (r < nrows) g_sm[((size_t)b*NN + n0 + r)*TT + t] = accs[r];
}

// ---------------- K5: polynomial epilogue -> new_values -------------------
__global__ __launch_bounds__(256) void k5(const float* __restrict__ gWout,
                                          float* __restrict__ out)
{
    int warp = threadIdx.x >> 5, lane = threadIdx.x & 31;
    int f0 = lane * 2;
    float2 c1 = *(const float2*)&g_coef[0][f0];
    float2 c2 = *(const float2*)&g_coef[1][f0];
    float2 c4 = *(const float2*)&g_coef[2][f0];
    float2 c6 = *(const float2*)&g_coef[3][f0];
    float2 c8 = *(const float2*)&g_coef[4][f0];
    float xs = g_xsafe;
    int stride = gridDim.x * 8;
    for (int row = blockIdx.x*8 + warp; row < BN*TT; row += stride) {
        float x = g_sm[row];
        float2 o;
        if (fabsf(x) <= xs) {
            float x2 = x*x;
            o.x = x*c1.x + x2*(c2.x + x2*(c4.x + x2*(c6.x + x2*c8.x)));
            o.y = x*c1.y + x2*(c2.y + x2*(c4.y + x2*(c6.y + x2*c8.y)));
        } else {
            o.x = 0.f; o.y = 0.f;
            for (int h = 0; h < 128; h++) {
                float u = g_gw[h] * x;
                float ge = 0.5f*u*(1.f + erff(u*0.70710678118f));
                float2 w = *(const float2*)&gWout[h*64 + f0];
                o.x += ge*w.x; o.y += ge*w.y;
            }
        }
        *(float2*)&out[(size_t)row*64 + f0] = o;
    }
}

// ---------------- launch ----------------------------------------------------
extern "C" void kernel_launch(void* const* d_in, const int* in_sizes, int n_in,
                              void* d_out, int out_size)
{
    const float* Q_in     = (const float*)d_in[0];
    const float* K_in     = (const float*)d_in[1];
    const float* V_in     = (const float*)d_in[2];
    const float* adj      = (const float*)d_in[3];
    const float* Wq       = (const float*)d_in[4];
    const float* Wk       = (const float*)d_in[5];
    const float* Wv       = (const float*)d_in[6];
    const float* Wout_map = (const float*)d_in[7];
    const float* gQ1      = (const float*)d_in[8];
    const float* gQ2      = (const float*)d_in[9];
    const float* gK1      = (const float*)d_in[10];
    const float* gK2      = (const float*)d_in[11];
    const float* gWa      = (const float*)d_in[12];
    const float* gWg      = (const float*)d_in[13];
    const float* gWout    = (const float*)d_in[14];
    float* out = (float*)d_out;

    // dependency order: k0 -> k1a -> k1bc -> k3 -> k4 -> k5 (nops are inert)
    k0<<<1, 256>>>(Wout_map, gWg, gWout, gQ2, gK2, gWa, Wq, Wk);  // idx 0
    knop1<<<1, 32>>>();                                           // idx 1
    knop2<<<1, 32>>>();                                           // idx 2
    k1a<<<BN, 256>>>(Q_in, K_in, out);                            // idx 3  <-- profiled
    k1bc<<<BN, 288>>>(V_in, Wv, gQ1, gK1);                        // idx 4
    dim3 g3(NN, BB);
    k3<<<g3, 352>>>(adj, out);                                    // idx 5
    dim3 g4((NN + 7) / 8, BB);
    k4<<<g4, 288>>>(out + OFF_ADJ2);                              // idx 6
    k5<<<1480, 256>>>(gWout, out);                                // idx 7
}

// round 13
// speedup vs baseline: 1.0349x; 1.0349x over previous
#include <cuda_runtime.h>
#include <math.h>

#define BB 4
#define NN 325
#define TT 288
#define FF 64
#define HH 8
#define LL 24
#define NTOP 5
#define BN (BB*NN)

#define OFF_DELAY (BB*NN*TT*FF)                 // 23961600
#define OFF_TMP   (OFF_DELAY + BN*HH*NTOP)      // +52000
#define OFF_ADJ2  (OFF_TMP + BN*HH*NTOP)        // +52000

// ---------------- scratch (static device globals; no runtime alloc) -------
__device__ float g_s[BN*TT];        // s[b,n,t]
__device__ float g_sm[BN*TT];       // sm[b,n,t] = adj2 @ s
__device__ float g_sq[BN];
__device__ float g_sk[BN];
__device__ float g_gw[128];
__device__ float g_coef[5][FF];     // poly coeffs a1,a2,a4,a6,a8
__device__ float g_xsafe;
__device__ float g_D[4];            // D[sigma][tau] = W_sigma . R_tau
__device__ __align__(16) float g_Wqp[HH*768];   // permuted Wq: [h][p*64+f]
__device__ __align__(16) float g_Wkp[HH*768];
__device__ float g_wtop[BN*HH*NTOP];
__device__ int   g_dtop[BN*HH*NTOP];
__device__ int   g_nopsink;

// ---------------- K0: weight precompute + conv-weight permute -------------
__global__ __launch_bounds__(256) void k0(
    const float* __restrict__ Wout_map, const float* __restrict__ gWg,
    const float* __restrict__ gWout, const float* __restrict__ gQ2,
    const float* __restrict__ gK2, const float* __restrict__ gWa,
    const float* __restrict__ Wq, const float* __restrict__ Wk)
{
    int tid = threadIdx.x;   // 256 threads
    __shared__ float ws[64], wp[64], wm[64];
    __shared__ float gsh[128];
    __shared__ float Pp[128], Pm[128], Rp[128], Rm[128];
    __shared__ float Wp[128], Wm[128];

    for (int i = tid; i < HH*768; i += 256) {
        int h = i / 768, r = i % 768, p = r >> 6, f = r & 63;
        g_Wqp[i] = Wq[h*768 + f*12 + p];
        g_Wkp[i] = Wk[h*768 + f*12 + p];
    }

    if (tid < 64) {
        float a = 0.f;
#pragma unroll
        for (int c = 0; c < 8; c++) a += Wout_map[tid*8 + c];
        ws[tid] = a;
        wp[tid] = fmaxf(a, 0.f);
        wm[tid] = fmaxf(-a, 0.f);
    }
    __syncthreads();
    if (tid < 128) {
        float a = 0.f;
        for (int f = 0; f < 64; f++) a += ws[f] * gWg[f*128 + tid];
        g_gw[tid] = a; gsh[tid] = a;
        float pp = 0.f, pm = 0.f, rp = 0.f, rm = 0.f;
        for (int f = 0; f < 64; f++) {
            float q = gQ2[tid*64 + f], k = gK2[tid*64 + f];
            pp += q * wp[f]; pm += q * wm[f];
            rp += k * wp[f]; rm += k * wm[f];
        }
        Pp[tid] = pp; Pm[tid] = pm; Rp[tid] = rp; Rm[tid] = rm;
    }
    __syncthreads();
    if (tid == 0) {
        float m = 0.f;
        for (int h = 0; h < 128; h++) m = fmaxf(m, fabsf(gsh[h]));
        g_xsafe = 0.68f / fmaxf(m, 1e-30f);
    }
    if (tid < 128) {
        float a = 0.f, b = 0.f;
        for (int h = 0; h < 128; h++) {
            float w = gWa[h*128 + tid];
            a += Pp[h] * w; b += Pm[h] * w;
        }
        Wp[tid] = a; Wm[tid] = b;
    }
    if (tid < 64) {
        float c1=0.f,c2=0.f,c4=0.f,c6=0.f,c8=0.f;
        for (int h = 0; h < 128; h++) {
            float g = gsh[h], w = gWout[h*64 + tid];
            float g2 = g*g, g4 = g2*g2;
            c1 += g*w; c2 += g2*w; c4 += g4*w; c6 += g4*g2*w; c8 += g4*g4*w;
        }
        const float C = 0.3989422804014327f;  // 1/sqrt(2*pi)
        g_coef[0][tid] =  0.5f*c1;
        g_coef[1][tid] =  C*c2;
        g_coef[2][tid] = -C*c4*(1.f/6.f);
        g_coef[3][tid] =  C*c6*(1.f/40.f);
        g_coef[4][tid] = -C*c8*(1.f/336.f);
    }
    __syncthreads();
    if (tid < 4) {
        int sg = tid >> 1, tu = tid & 1;
        const float* Wv = sg ? Wm : Wp;
        const float* Rv = tu ? Rm : Rp;
        float d = 0.f;
        for (int j = 0; j < 128; j++) d += Wv[j] * Rv[j];
        g_D[tid] = d;
    }
}

// ---------------- nop filler ------------------------------------------------
__global__ void knop1() { if (threadIdx.x == 1024) g_nopsink = 1; }

// ---------------- K1a: q/k projection + corr + topk + softmax -------------
// 256 threads = 8 warps; warp w handles patches 3w..3w+2 (R3 proven config).
__global__ __launch_bounds__(256) void k1a(
    const float* __restrict__ Qin, const float* __restrict__ Kin,
    float* __restrict__ out)
{
    __shared__ __align__(16) float4 Wq4[HH*192];   // 24 KB
    __shared__ __align__(16) float4 Wk4[HH*192];   // 24 KB
    __shared__ float qh[192], kh[192], corr[192];

    int bn   = blockIdx.x;
    int tid  = threadIdx.x;
    int w    = tid >> 5, lane = tid & 31;
    const float4* Qb = reinterpret_cast<const float4*>(Qin) + (size_t)bn * (TT*FF/4);
    const float4* Kb = reinterpret_cast<const float4*>(Kin) + (size_t)bn * (TT*FF/4);

    const float4* wq_g = reinterpret_cast<const float4*>(g_Wqp);
    const float4* wk_g = reinterpret_cast<const float4*>(g_Wkp);
    for (int i = tid; i < HH*192; i += 256) { Wq4[i] = wq_g[i]; Wk4[i] = wk_g[i]; }
    __syncthreads();

    int l0 = w * 3;
    // ---- Q pass ----
    {
        float acc[3][8];
#pragma unroll
        for (int j = 0; j < 3; j++)
#pragma unroll
            for (int h = 0; h < 8; h++) acc[j][h] = 0.f;
#pragma unroll
        for (int it = 0; it < 6; it++) {
            float4 d0 = Qb[(l0+0)*192 + it*32 + lane];
            float4 d1 = Qb[(l0+1)*192 + it*32 + lane];
            float4 d2 = Qb[(l0+2)*192 + it*32 + lane];
#pragma unroll
            for (int h = 0; h < 8; h++) {
                float4 wv = Wq4[h*192 + it*32 + lane];
                acc[0][h] += d0.x*wv.x + d0.y*wv.y + d0.z*wv.z + d0.w*wv.w;
                acc[1][h] += d1.x*wv.x + d1.y*wv.y + d1.z*wv.z + d1.w*wv.w;
                acc[2][h] += d2.x*wv.x + d2.y*wv.y + d2.z*wv.z + d2.w*wv.w;
            }
        }
#pragma unroll
        for (int j = 0; j < 3; j++)
#pragma unroll
            for (int h = 0; h < 8; h++) {
                float a = acc[j][h];
#pragma unroll
                for (int o = 16; o; o >>= 1) a += __shfl_xor_sync(0xffffffffu, a, o);
                if (lane == 0) qh[h*24 + l0 + j] = a;
            }
    }
    // ---- K pass ----
    {
        float acc[3][8];
#pragma unroll
        for (int j = 0; j < 3; j++)
#pragma unroll
            for (int h = 0; h < 8; h++) acc[j][h] = 0.f;
#pragma unroll
        for (int it = 0; it < 6; it++) {
            float4 d0 = Kb[(l0+0)*192 + it*32 + lane];
            float4 d1 = Kb[(l0+1)*192 + it*32 + lane];
            float4 d2 = Kb[(l0+2)*192 + it*32 + lane];
#pragma unroll
            for (int h = 0; h < 8; h++) {
                float4 wv = Wk4[h*192 + it*32 + lane];
                acc[0][h] += d0.x*wv.x + d0.y*wv.y + d0.z*wv.z + d0.w*wv.w;
                acc[1][h] += d1.x*wv.x + d1.y*wv.y + d1.z*wv.z + d1.w*wv.w;
                acc[2][h] += d2.x*wv.x + d2.y*wv.y + d2.z*wv.z + d2.w*wv.w;
            }
        }
#pragma unroll
        for (int j = 0; j < 3; j++)
#pragma unroll
            for (int h = 0; h < 8; h++) {
                float a = acc[j][h];
#pragma unroll
                for (int o = 16; o; o >>= 1) a += __shfl_xor_sync(0xffffffffu, a, o);
                if (lane == 0) kh[h*24 + l0 + j] = a;
            }
    }
    __syncthreads();

    // circular correlation: corr[h][d] = sum_m q[(m+d)%24]*k[m]
    if (tid < 192) {
        int h = tid / 24, d = tid % 24;
        float a = 0.f;
#pragma unroll
        for (int m = 0; m < 24; m++) {
            int i = m + d; if (i >= 24) i -= 24;
            a += qh[h*24 + i] * kh[h*24 + m];
        }
        corr[h*24 + d] = a;
    }
    __syncthreads();

    // top-5 per head (strict > keeps lowest index on ties, like lax.top_k)
    if (tid < 8) {
        int h = tid;
        float vals[24];
#pragma unroll
        for (int d = 0; d < 24; d++) vals[d] = corr[h*24 + d];
        float wv[5]; int dd[5];
#pragma unroll
        for (int i = 0; i < 5; i++) {
            float best = -1e30f; int bd = 0;
#pragma unroll
            for (int d = 0; d < 24; d++) if (vals[d] > best) { best = vals[d]; bd = d; }
            wv[i] = best; dd[i] = bd; vals[bd] = -1e30f;
        }
        float mx = wv[0], s = 0.f, e[5];
#pragma unroll
        for (int i = 0; i < 5; i++) { e[i] = expf(wv[i] - mx); s += e[i]; }
        float inv = 1.f / s;
#pragma unroll
        for (int i = 0; i < 5; i++) {
            float ww = e[i] * inv;
            g_wtop[(bn*8 + h)*5 + i] = ww;
            g_dtop[(bn*8 + h)*5 + i] = dd[i];
            out[OFF_DELAY + (bn*8 + h)*5 + i] = (float)(dd[i] * 12);
            out[OFF_TMP   + (bn*8 + h)*5 + i] = ww;
        }
    }
}

// ---------------- K1bc: fused v_small + delay aggregation (R4 staged) -----
__global__ __launch_bounds__(288) void k1bc(const float* __restrict__ Vin,
                                            const float* __restrict__ Wv,
                                            const float* __restrict__ gQ1,
                                            const float* __restrict__ gK1)
{
    __shared__ __align__(16) float Vs[TT*68];    // 78336 B (stride 17 float4)
    __shared__ float vs[TT*9];                   // 10368 B
    __shared__ __align__(16) float Wvs[8*68];    // 2176 B
    __shared__ float wt[40];
    __shared__ int   dt[40];
    __shared__ float red1[9], red2[9];

    int bn = blockIdx.x, tid = threadIdx.x;
    int warp = tid >> 5, lane = tid & 31;

    if (tid < 128) {
        int h = tid >> 4, c4 = tid & 15;
        reinterpret_cast<float4*>(Wvs)[h*17 + c4] =
            reinterpret_cast<const float4*>(Wv)[h*16 + c4];
    }
    if (tid < 40) { wt[tid] = g_wtop[bn*40 + tid]; dt[tid] = g_dtop[bn*40 + tid]; }

    {
        const float4* src = reinterpret_cast<const float4*>(Vin) + (size_t)bn * (TT*FF/4);
        float4* dst = reinterpret_cast<float4*>(Vs);
#pragma unroll
        for (int k = 0; k < 16; k++) {
            int idx = tid + k*288;
            float4 v = src[idx];
            int r = idx >> 4, c4 = idx & 15;
            dst[r*17 + c4] = v;
        }
    }
    __syncthreads();

    {
        int t = tid;
        float acc[8] = {0.f,0.f,0.f,0.f,0.f,0.f,0.f,0.f};
        const float4* vrow = reinterpret_cast<const float4*>(Vs) + t*17;
        const float4* wv4  = reinterpret_cast<const float4*>(Wvs);
#pragma unroll
        for (int f4 = 0; f4 < 16; f4++) {
            float4 v = vrow[f4];
#pragma unroll
            for (int h = 0; h < 8; h++) {
                float4 w = wv4[h*17 + f4];
                acc[h] += v.x*w.x + v.y*w.y + v.z*w.z + v.w*w.w;
            }
        }
#pragma unroll
        for (int h = 0; h < 8; h++) vs[t*9 + h] = acc[h];
    }
    __syncthreads();

    {
        int t = tid;
        float sv = 0.f;
#pragma unroll
        for (int h = 0; h < 8; h++)
#pragma unroll
            for (int i = 0; i < 5; i++) {
                int idx = dt[h*5 + i]*12 + t; if (idx >= 288) idx -= 288;
                sv += wt[h*5 + i] * vs[idx*9 + h];
            }
        sv *= 0.125f;
        g_s[bn*288 + t] = sv;
        float pq = sv * __ldg(gQ1 + t);
        float pk = sv * __ldg(gK1 + t);
#pragma unroll
        for (int o = 16; o; o >>= 1) {
            pq += __shfl_xor_sync(0xffffffffu, pq, o);
            pk += __shfl_xor_sync(0xffffffffu, pk, o);
        }
        if (lane == 0) { red1[warp] = pq; red2[warp] = pk; }
    }
    __syncthreads();
    if (tid == 0) {
        float a = 0.f, b2 = 0.f;
#pragma unroll
        for (int w2 = 0; w2 < 9; w2++) { a += red1[w2]; b2 += red2[w2]; }
        g_sq[bn] = a; g_sk[bn] = b2;
    }
}

// ---------------- K3: rank-2 attention logits + softmax * adj -> adj2 -----
__global__ __launch_bounds__(352) void k3(const float* __restrict__ adj,
                                          float* __restrict__ out)
{
    __shared__ float red[11];
    int n = blockIdx.x, b = blockIdx.y;
    int bn = b*NN + n;
    int tid = threadIdx.x, w = tid >> 5, lane = tid & 31;

    float sq = g_sq[bn];
    float c  = fabsf(sq);
    const float d0 = (sq < 0.f) ? g_D[2] : g_D[0];
    const float d1 = (sq < 0.f) ? g_D[3] : g_D[1];

    float x = -1e30f;
    if (tid < NN) {
        float sk = g_sk[b*NN + tid];
        x = c * fabsf(sk) * (sk < 0.f ? d1 : d0);
    }
    float mx = x;
#pragma unroll
    for (int o = 16; o; o >>= 1) mx = fmaxf(mx, __shfl_xor_sync(0xffffffffu, mx, o));
    if (lane == 0) red[w] = mx;
    __syncthreads();
    {
        float m2 = -1e30f;
#pragma unroll
        for (int i = 0; i < 11; i++) m2 = fmaxf(m2, red[i]);
        mx = m2;
    }
    __syncthreads();
    float e = (tid < NN) ? expf(x - mx) : 0.f;
    float s = e;
#pragma unroll
    for (int o = 16; o; o >>= 1) s += __shfl_xor_sync(0xffffffffu, s, o);
    if (lane == 0) red[w] = s;
    __syncthreads();
    {
        float s2 = 0.f;
#pragma unroll
        for (int i = 0; i < 11; i++) s2 += red[i];
        s = s2;
    }
    if (tid < NN)
        out[OFF_ADJ2 + (size_t)bn*NN + tid] = e * (1.f / s) * __ldg(adj + n*NN + tid);
}

// ---------------- K4: sm = adj2 @ s (8 rows/block, plain FMA, no asm) -----
__global__ __launch_bounds__(288) void k4(const float* __restrict__ adj2)
{
    int b = blockIdx.y, n0 = blockIdx.x * 8;
    int nrows = NN - n0; if (nrows > 8) nrows = 8;
    __shared__ __align__(16) float art[NN*8];    // transposed: art[m*8 + r]
    int tid = threadIdx.x;
    const float* src = adj2 + ((size_t)b*NN + n0)*NN;
    for (int i = tid; i < 8*NN; i += 288) {
        int r = i / NN, m = i - r*NN;
        art[m*8 + r] = (r < nrows) ? src[i] : 0.f;
    }
    __syncthreads();

    int t = tid;
    float a0=0.f,a1=0.f,a2=0.f,a3=0.f,a4=0.f,a5=0.f,a6=0.f,a7=0.f;
    const float* sb = g_s + (size_t)b*NN*TT;
#pragma unroll 10
    for (int m = 0; m < NN; m++) {
        float sv = sb[m*TT + t];
        a0 += art[m*8 + 0] * sv;
        a1 += art[m*8 + 1] * sv;
        a2 += art[m*8 + 2] * sv;
        a3 += art[m*8 + 3] * sv;
        a4 += art[m*8 + 4] * sv;
        a5 += art[m*8 + 5] * sv;
        a6 += art[m*8 + 6] * sv;
        a7 += art[m*8 + 7] * sv;
    }
    float accs[8] = {a0,a1,a2,a3,a4,a5,a6,a7};
#pragma unroll
    for (int r = 0; r < 8; r++)
        if (r < nrows) g_sm[((size_t)b*NN + n0 + r)*TT + t] = accs[r];
}

// ---------------- K5: polynomial epilogue -> new_values (STG.128) ---------
// Each warp handles 2 rows per iteration: lanes 0-15 row A, 16-31 row B.
// Each lane stores one float4 (16 lanes cover 64 floats).
__global__ __launch_bounds__(256) void k5(const float* __restrict__ gWout,
                                          float* __restrict__ out)
{
    int warp = threadIdx.x >> 5, lane = threadIdx.x & 31;
    int f0 = (lane & 15) * 4;
    int rsel = lane >> 4;          // 0 or 1
    float4 c1 = *(const float4*)&g_coef[0][f0];
    float4 c2 = *(const float4*)&g_coef[1][f0];
    float4 c4 = *(const float4*)&g_coef[2][f0];
    float4 c6 = *(const float4*)&g_coef[3][f0];
    float4 c8 = *(const float4*)&g_coef[4][f0];
    float xs = g_xsafe;
    int stride = gridDim.x * 8;
    for (int r2 = blockIdx.x*8 + warp; r2 < (BN*TT)/2; r2 += stride) {
        int row = r2*2 + rsel;
        float x = g_sm[row];
        float4 o;
        if (fabsf(x) <= xs) {
            float x2 = x*x;
            o.x = x*c1.x + x2*(c2.x + x2*(c4.x + x2*(c6.x + x2*c8.x)));
            o.y = x*c1.y + x2*(c2.y + x2*(c4.y + x2*(c6.y + x2*c8.y)));
            o.z = x*c1.z + x2*(c2.z + x2*(c4.z + x2*(c6.z + x2*c8.z)));
            o.w = x*c1.w + x2*(c2.w + x2*(c4.w + x2*(c6.w + x2*c8.w)));
        } else {
            o.x = 0.f; o.y = 0.f; o.z = 0.f; o.w = 0.f;
            for (int h = 0; h < 128; h++) {
                float u = g_gw[h] * x;
                float ge = 0.5f*u*(1.f + erff(u*0.70710678118f));
                float4 w = *(const float4*)&gWout[h*64 + f0];
                o.x += ge*w.x; o.y += ge*w.y; o.z += ge*w.z; o.w += ge*w.w;
            }
        }
        *(float4*)&out[(size_t)row*64 + f0] = o;
    }
}

// ---------------- launch ----------------------------------------------------
extern "C" void kernel_launch(void* const* d_in, const int* in_sizes, int n_in,
                              void* d_out, int out_size)
{
    const float* Q_in     = (const float*)d_in[0];
    const float* K_in     = (const float*)d_in[1];
    const float* V_in     = (const float*)d_in[2];
    const float* adj      = (const float*)d_in[3];
    const float* Wq       = (const float*)d_in[4];
    const float* Wk       = (const float*)d_in[5];
    const float* Wv       = (const float*)d_in[6];
    const float* Wout_map = (const float*)d_in[7];
    const float* gQ1      = (const float*)d_in[8];
    const float* gQ2      = (const float*)d_in[9];
    const float* gK1      = (const float*)d_in[10];
    const float* gK2      = (const float*)d_in[11];
    const float* gWa      = (const float*)d_in[12];
    const float* gWg      = (const float*)d_in[13];
    const float* gWout    = (const float*)d_in[14];
    float* out = (float*)d_out;

    // dependency order: k0 -> k1a -> k1bc -> k3 -> k4 -> k5 (nop inert)
    k0<<<1, 256>>>(Wout_map, gWg, gWout, gQ2, gK2, gWa, Wq, Wk);  // idx 0
    k1a<<<BN, 256>>>(Q_in, K_in, out);                            // idx 1
    knop1<<<1, 32>>>();                                           // idx 2
    k1bc<<<BN, 288>>>(V_in, Wv, gQ1, gK1);                        // idx 3  <-- profiled
    dim3 g3(NN, BB);
    k3<<<g3, 352>>>(adj, out);                                    // idx 4
    dim3 g4((NN + 7) / 8, BB);
    k4<<<g4, 288>>>(out + OFF_ADJ2);                              // idx 5
    k5<<<1480, 256>>>(gWout, out);                                // idx 6
}

// round 14
// speedup vs baseline: 1.0467x; 1.0114x over previous
#include <cuda_runtime.h>
#include <math.h>

#define BB 4
#define NN 325
#define TT 288
#define FF 64
#define HH 8
#define LL 24
#define NTOP 5
#define BN (BB*NN)

#define OFF_DELAY (BB*NN*TT*FF)                 // 23961600
#define OFF_TMP   (OFF_DELAY + BN*HH*NTOP)      // +52000
#define OFF_ADJ2  (OFF_TMP + BN*HH*NTOP)        // +52000

// ---------------- scratch (static device globals; no runtime alloc) -------
__device__ float g_s[BN*TT];        // s[b,n,t]
__device__ float g_sm[BN*TT];       // sm[b,n,t] = adj2 @ s
__device__ float g_sq[BN];
__device__ float g_sk[BN];
__device__ float g_gw[128];
__device__ float g_coef[5][FF];     // poly coeffs a1,a2,a4,a6,a8
__device__ float g_xsafe;
__device__ float g_D[4];            // D[sigma][tau] = W_sigma . R_tau
__device__ __align__(16) float g_Wqp[HH*768];   // permuted Wq: [h][p*64+f]
__device__ __align__(16) float g_Wkp[HH*768];
__device__ float g_wtop[BN*HH*NTOP];
__device__ int   g_dtop[BN*HH*NTOP];

// ---------------- K0: weight precompute + conv-weight permute -------------
__global__ __launch_bounds__(256) void k0(
    const float* __restrict__ Wout_map, const float* __restrict__ gWg,
    const float* __restrict__ gWout, const float* __restrict__ gQ2,
    const float* __restrict__ gK2, const float* __restrict__ gWa,
    const float* __restrict__ Wq, const float* __restrict__ Wk)
{
    int tid = threadIdx.x;   // 256 threads
    __shared__ float ws[64], wp[64], wm[64];
    __shared__ float gsh[128];
    __shared__ float Pp[128], Pm[128], Rp[128], Rm[128];
    __shared__ float Wp[128], Wm[128];

    for (int i = tid; i < HH*768; i += 256) {
        int h = i / 768, r = i % 768, p = r >> 6, f = r & 63;
        g_Wqp[i] = Wq[h*768 + f*12 + p];
        g_Wkp[i] = Wk[h*768 + f*12 + p];
    }

    if (tid < 64) {
        float a = 0.f;
#pragma unroll
        for (int c = 0; c < 8; c++) a += Wout_map[tid*8 + c];
        ws[tid] = a;
        wp[tid] = fmaxf(a, 0.f);
        wm[tid] = fmaxf(-a, 0.f);
    }
    __syncthreads();
    if (tid < 128) {
        float a = 0.f;
        for (int f = 0; f < 64; f++) a += ws[f] * gWg[f*128 + tid];
        g_gw[tid] = a; gsh[tid] = a;
        float pp = 0.f, pm = 0.f, rp = 0.f, rm = 0.f;
        for (int f = 0; f < 64; f++) {
            float q = gQ2[tid*64 + f], k = gK2[tid*64 + f];
            pp += q * wp[f]; pm += q * wm[f];
            rp += k * wp[f]; rm += k * wm[f];
        }
        Pp[tid] = pp; Pm[tid] = pm; Rp[tid] = rp; Rm[tid] = rm;
    }
    __syncthreads();
    if (tid == 0) {
        float m = 0.f;
        for (int h = 0; h < 128; h++) m = fmaxf(m, fabsf(gsh[h]));
        g_xsafe = 0.68f / fmaxf(m, 1e-30f);
    }
    if (tid < 128) {
        float a = 0.f, b = 0.f;
        for (int h = 0; h < 128; h++) {
            float w = gWa[h*128 + tid];
            a += Pp[h] * w; b += Pm[h] * w;
        }
        Wp[tid] = a; Wm[tid] = b;
    }
    if (tid < 64) {
        float c1=0.f,c2=0.f,c4=0.f,c6=0.f,c8=0.f;
        for (int h = 0; h < 128; h++) {
            float g = gsh[h], w = gWout[h*64 + tid];
            float g2 = g*g, g4 = g2*g2;
            c1 += g*w; c2 += g2*w; c4 += g4*w; c6 += g4*g2*w; c8 += g4*g4*w;
        }
        const float C = 0.3989422804014327f;  // 1/sqrt(2*pi)
        g_coef[0][tid] =  0.5f*c1;
        g_coef[1][tid] =  C*c2;
        g_coef[2][tid] = -C*c4*(1.f/6.f);
        g_coef[3][tid] =  C*c6*(1.f/40.f);
        g_coef[4][tid] = -C*c8*(1.f/336.f);
    }
    __syncthreads();
    if (tid < 4) {
        int sg = tid >> 1, tu = tid & 1;
        const float* Wv = sg ? Wm : Wp;
        const float* Rv = tu ? Rm : Rp;
        float d = 0.f;
        for (int j = 0; j < 128; j++) d += Wv[j] * Rv[j];
        g_D[tid] = d;
    }
}

// ---------------- K1a: q/k projection + corr + topk + softmax -------------
// 256 threads = 8 warps; warp w handles patches 3w..3w+2 (R3 proven config).
__global__ __launch_bounds__(256) void k1a(
    const float* __restrict__ Qin, const float* __restrict__ Kin,
    float* __restrict__ out)
{
    __shared__ __align__(16) float4 Wq4[HH*192];   // 24 KB
    __shared__ __align__(16) float4 Wk4[HH*192];   // 24 KB
    __shared__ float qh[192], kh[192], corr[192];

    int bn   = blockIdx.x;
    int tid  = threadIdx.x;
    int w    = tid >> 5, lane = tid & 31;
    const float4* Qb = reinterpret_cast<const float4*>(Qin) + (size_t)bn * (TT*FF/4);
    const float4* Kb = reinterpret_cast<const float4*>(Kin) + (size_t)bn * (TT*FF/4);

    const float4* wq_g = reinterpret_cast<const float4*>(g_Wqp);
    const float4* wk_g = reinterpret_cast<const float4*>(g_Wkp);
    for (int i = tid; i < HH*192; i += 256) { Wq4[i] = wq_g[i]; Wk4[i] = wk_g[i]; }
    __syncthreads();

    int l0 = w * 3;
    // ---- Q pass ----
    {
        float acc[3][8];
#pragma unroll
        for (int j = 0; j < 3; j++)
#pragma unroll
            for (int h = 0; h < 8; h++) acc[j][h] = 0.f;
#pragma unroll
        for (int it = 0; it < 6; it++) {
            float4 d0 = Qb[(l0+0)*192 + it*32 + lane];
            float4 d1 = Qb[(l0+1)*192 + it*32 + lane];
            float4 d2 = Qb[(l0+2)*192 + it*32 + lane];
#pragma unroll
            for (int h = 0; h < 8; h++) {
                float4 wv = Wq4[h*192 + it*32 + lane];
                acc[0][h] += d0.x*wv.x + d0.y*wv.y + d0.z*wv.z + d0.w*wv.w;
                acc[1][h] += d1.x*wv.x + d1.y*wv.y + d1.z*wv.z + d1.w*wv.w;
                acc[2][h] += d2.x*wv.x + d2.y*wv.y + d2.z*wv.z + d2.w*wv.w;
            }
        }
#pragma unroll
        for (int j = 0; j < 3; j++)
#pragma unroll
            for (int h = 0; h < 8; h++) {
                float a = acc[j][h];
#pragma unroll
                for (int o = 16; o; o >>= 1) a += __shfl_xor_sync(0xffffffffu, a, o);
                if (lane == 0) qh[h*24 + l0 + j] = a;
            }
    }
    // ---- K pass ----
    {
        float acc[3][8];
#pragma unroll
        for (int j = 0; j < 3; j++)
#pragma unroll
            for (int h = 0; h < 8; h++) acc[j][h] = 0.f;
#pragma unroll
        for (int it = 0; it < 6; it++) {
            float4 d0 = Kb[(l0+0)*192 + it*32 + lane];
            float4 d1 = Kb[(l0+1)*192 + it*32 + lane];
            float4 d2 = Kb[(l0+2)*192 + it*32 + lane];
#pragma unroll
            for (int h = 0; h < 8; h++) {
                float4 wv = Wk4[h*192 + it*32 + lane];
                acc[0][h] += d0.x*wv.x + d0.y*wv.y + d0.z*wv.z + d0.w*wv.w;
                acc[1][h] += d1.x*wv.x + d1.y*wv.y + d1.z*wv.z + d1.w*wv.w;
                acc[2][h] += d2.x*wv.x + d2.y*wv.y + d2.z*wv.z + d2.w*wv.w;
            }
        }
#pragma unroll
        for (int j = 0; j < 3; j++)
#pragma unroll
            for (int h = 0; h < 8; h++) {
                float a = acc[j][h];
#pragma unroll
                for (int o = 16; o; o >>= 1) a += __shfl_xor_sync(0xffffffffu, a, o);
                if (lane == 0) kh[h*24 + l0 + j] = a;
            }
    }
    __syncthreads();

    // circular correlation: corr[h][d] = sum_m q[(m+d)%24]*k[m]
    if (tid < 192) {
        int h = tid / 24, d = tid % 24;
        float a = 0.f;
#pragma unroll
        for (int m = 0; m < 24; m++) {
            int i = m + d; if (i >= 24) i -= 24;
            a += qh[h*24 + i] * kh[h*24 + m];
        }
        corr[h*24 + d] = a;
    }
    __syncthreads();

    // top-5 per head (strict > keeps lowest index on ties, like lax.top_k)
    if (tid < 8) {
        int h = tid;
        float vals[24];
#pragma unroll
        for (int d = 0; d < 24; d++) vals[d] = corr[h*24 + d];
        float wv[5]; int dd[5];
#pragma unroll
        for (int i = 0; i < 5; i++) {
            float best = -1e30f; int bd = 0;
#pragma unroll
            for (int d = 0; d < 24; d++) if (vals[d] > best) { best = vals[d]; bd = d; }
            wv[i] = best; dd[i] = bd; vals[bd] = -1e30f;
        }
        float mx = wv[0], s = 0.f, e[5];
#pragma unroll
        for (int i = 0; i < 5; i++) { e[i] = expf(wv[i] - mx); s += e[i]; }
        float inv = 1.f / s;
#pragma unroll
        for (int i = 0; i < 5; i++) {
            float ww = e[i] * inv;
            g_wtop[(bn*8 + h)*5 + i] = ww;
            g_dtop[(bn*8 + h)*5 + i] = dd[i];
            out[OFF_DELAY + (bn*8 + h)*5 + i] = (float)(dd[i] * 12);
            out[OFF_TMP   + (bn*8 + h)*5 + i] = ww;
        }
    }
}

// ---------------- K1bc: fused v_small + delay aggregation (R4 staged) -----
__global__ __launch_bounds__(288) void k1bc(const float* __restrict__ Vin,
                                            const float* __restrict__ Wv,
                                            const float* __restrict__ gQ1,
                                            const float* __restrict__ gK1)
{
    __shared__ __align__(16) float Vs[TT*68];    // 78336 B (stride 17 float4)
    __shared__ float vs[TT*9];                   // 10368 B
    __shared__ __align__(16) float Wvs[8*68];    // 2176 B
    __shared__ float wt[40];
    __shared__ int   dt[40];
    __shared__ float red1[9], red2[9];

    int bn = blockIdx.x, tid = threadIdx.x;
    int warp = tid >> 5, lane = tid & 31;

    if (tid < 128) {
        int h = tid >> 4, c4 = tid & 15;
        reinterpret_cast<float4*>(Wvs)[h*17 + c4] =
            reinterpret_cast<const float4*>(Wv)[h*16 + c4];
    }
    if (tid < 40) { wt[tid] = g_wtop[bn*40 + tid]; dt[tid] = g_dtop[bn*40 + tid]; }

    {
        const float4* src = reinterpret_cast<const float4*>(Vin) + (size_t)bn * (TT*FF/4);
        float4* dst = reinterpret_cast<float4*>(Vs);
#pragma unroll
        for (int k = 0; k < 16; k++) {
            int idx = tid + k*288;
            float4 v = src[idx];
            int r = idx >> 4, c4 = idx & 15;
            dst[r*17 + c4] = v;
        }
    }
    __syncthreads();

    {
        int t = tid;
        float acc[8] = {0.f,0.f,0.f,0.f,0.f,0.f,0.f,0.f};
        const float4* vrow = reinterpret_cast<const float4*>(Vs) + t*17;
        const float4* wv4  = reinterpret_cast<const float4*>(Wvs);
#pragma unroll
        for (int f4 = 0; f4 < 16; f4++) {
            float4 v = vrow[f4];
#pragma unroll
            for (int h = 0; h < 8; h++) {
                float4 w = wv4[h*17 + f4];
                acc[h] += v.x*w.x + v.y*w.y + v.z*w.z + v.w*w.w;
            }
        }
#pragma unroll
        for (int h = 0; h < 8; h++) vs[t*9 + h] = acc[h];
    }
    __syncthreads();

    {
        int t = tid;
        float sv = 0.f;
#pragma unroll
        for (int h = 0; h < 8; h++)
#pragma unroll
            for (int i = 0; i < 5; i++) {
                int idx = dt[h*5 + i]*12 + t; if (idx >= 288) idx -= 288;
                sv += wt[h*5 + i] * vs[idx*9 + h];
            }
        sv *= 0.125f;
        g_s[bn*288 + t] = sv;
        float pq = sv * __ldg(gQ1 + t);
        float pk = sv * __ldg(gK1 + t);
#pragma unroll
        for (int o = 16; o; o >>= 1) {
            pq += __shfl_xor_sync(0xffffffffu, pq, o);
            pk += __shfl_xor_sync(0xffffffffu, pk, o);
        }
        if (lane == 0) { red1[warp] = pq; red2[warp] = pk; }
    }
    __syncthreads();
    if (tid == 0) {
        float a = 0.f, b2 = 0.f;
#pragma unroll
        for (int w2 = 0; w2 < 9; w2++) { a += red1[w2]; b2 += red2[w2]; }
        g_sq[bn] = a; g_sk[bn] = b2;
    }
}

// ---------------- K34: rank-2 softmax*adj + GEMV (fused, plain FMA) -------
// grid (41, 4), 288 threads. Rows n0..n0+7.
__global__ __launch_bounds__(288) void k34(const float* __restrict__ adj,
                                           float* __restrict__ out)
{
    __shared__ float y0[NN], y1[NN];
    __shared__ __align__(16) float art[NN*8];   // adj2 transposed: art[m*8+r]
    __shared__ float redm0[9], redm1[9];
    __shared__ float ym0s, ym1s;

    int b = blockIdx.y, n0 = blockIdx.x * 8;
    int nrows = NN - n0; if (nrows > 8) nrows = 8;
    int tid = threadIdx.x, w = tid >> 5, lane = tid & 31;

    float D0 = g_D[0], D1 = g_D[1], D2 = g_D[2], D3 = g_D[3];
    float lm0 = -1e30f, lm1 = -1e30f;
    for (int m = tid; m < NN; m += 288) {
        float sk = g_sk[b*NN + m];
        float a  = fabsf(sk);
        float v0 = a * (sk < 0.f ? D1 : D0);
        float v1 = a * (sk < 0.f ? D3 : D2);
        y0[m] = v0; y1[m] = v1;
        lm0 = fmaxf(lm0, v0); lm1 = fmaxf(lm1, v1);
        // zero art columns for missing rows (last tile)
        if (nrows < 8)
            for (int r = nrows; r < 8; r++) art[m*8 + r] = 0.f;
    }
#pragma unroll
    for (int o = 16; o; o >>= 1) {
        lm0 = fmaxf(lm0, __shfl_xor_sync(0xffffffffu, lm0, o));
        lm1 = fmaxf(lm1, __shfl_xor_sync(0xffffffffu, lm1, o));
    }
    if (lane == 0) { redm0[w] = lm0; redm1[w] = lm1; }
    __syncthreads();
    if (tid == 0) {
        float a = -1e30f, c = -1e30f;
#pragma unroll
        for (int i = 0; i < 9; i++) { a = fmaxf(a, redm0[i]); c = fmaxf(c, redm1[i]); }
        ym0s = a; ym1s = c;
    }
    __syncthreads();

    // warp r handles row n0+r (softmax + adj product)
    if (w < nrows) {
        int n = n0 + w, bn = b*NN + n;
        float sq = g_sq[bn];
        float c  = fabsf(sq);
        const float* y  = (sq < 0.f) ? y1 : y0;
        float ym        = (sq < 0.f) ? ym1s : ym0s;
        float s = 0.f;
        for (int m = lane; m < NN; m += 32) {
            float e = expf(c * (y[m] - ym));
            art[m*8 + w] = e; s += e;
        }
#pragma unroll
        for (int o = 16; o; o >>= 1) s += __shfl_xor_sync(0xffffffffu, s, o);
        float inv = 1.f / s;
        for (int m = lane; m < NN; m += 32) {
            float a = art[m*8 + w] * inv * __ldg(adj + n*NN + m);
            art[m*8 + w] = a;
            out[OFF_ADJ2 + (size_t)bn*NN + m] = a;
        }
    }
    __syncthreads();

    // GEMV: sm[n0+r][t] = sum_m art[m][r] * s[b][m][t]  (plain FMA, no asm)
    {
        int t = tid;
        float a0=0.f,a1=0.f,a2=0.f,a3=0.f,a4=0.f,a5=0.f,a6=0.f,a7=0.f;
        const float* sb = g_s + (size_t)b*NN*TT;
#pragma unroll 10
        for (int m = 0; m < NN; m++) {
            float sv = sb[m*TT + t];
            a0 += art[m*8 + 0] * sv;
            a1 += art[m*8 + 1] * sv;
            a2 += art[m*8 + 2] * sv;
            a3 += art[m*8 + 3] * sv;
            a4 += art[m*8 + 4] * sv;
            a5 += art[m*8 + 5] * sv;
            a6 += art[m*8 + 6] * sv;
            a7 += art[m*8 + 7] * sv;
        }
        float accs[8] = {a0,a1,a2,a3,a4,a5,a6,a7};
#pragma unroll
        for (int r = 0; r < 8; r++)
            if (r < nrows) g_sm[((size_t)b*NN + n0 + r)*TT + t] = accs[r];
    }
}

// ---------------- K5: polynomial epilogue -> new_values (STG.128) ---------
__global__ __launch_bounds__(256) void k5(const float* __restrict__ gWout,
                                          float* __restrict__ out)
{
    int warp = threadIdx.x >> 5, lane = threadIdx.x & 31;
    int f0 = (lane & 15) * 4;
    int rsel = lane >> 4;          // 0 or 1
    float4 c1 = *(const float4*)&g_coef[0][f0];
    float4 c2 = *(const float4*)&g_coef[1][f0];
    float4 c4 = *(const float4*)&g_coef[2][f0];
    float4 c6 = *(const float4*)&g_coef[3][f0];
    float4 c8 = *(const float4*)&g_coef[4][f0];
    float xs = g_xsafe;
    int stride = gridDim.x * 8;
    for (int r2 = blockIdx.x*8 + warp; r2 < (BN*TT)/2; r2 += stride) {
        int row = r2*2 + rsel;
        float x = g_sm[row];
        float4 o;
        if (fabsf(x) <= xs) {
            float x2 = x*x;
            o.x = x*c1.x + x2*(c2.x + x2*(c4.x + x2*(c6.x + x2*c8.x)));
            o.y = x*c1.y + x2*(c2.y + x2*(c4.y + x2*(c6.y + x2*c8.y)));
            o.z = x*c1.z + x2*(c2.z + x2*(c4.z + x2*(c6.z + x2*c8.z)));
            o.w = x*c1.w + x2*(c2.w + x2*(c4.w + x2*(c6.w + x2*c8.w)));
        } else {
            o.x = 0.f; o.y = 0.f; o.z = 0.f; o.w = 0.f;
            for (int h = 0; h < 128; h++) {
                float u = g_gw[h] * x;
                float ge = 0.5f*u*(1.f + erff(u*0.70710678118f));
                float4 w = *(const float4*)&gWout[h*64 + f0];
                o.x += ge*w.x; o.y += ge*w.y; o.z += ge*w.z; o.w += ge*w.w;
            }
        }
        *(float4*)&out[(size_t)row*64 + f0] = o;
    }
}

// ---------------- launch ----------------------------------------------------
extern "C" void kernel_launch(void* const* d_in, const int* in_sizes, int n_in,
                              void* d_out, int out_size)
{
    const float* Q_in     = (const float*)d_in[0];
    const float* K_in     = (const float*)d_in[1];
    const float* V_in     = (const float*)d_in[2];
    const float* adj      = (const float*)d_in[3];
    const float* Wq       = (const float*)d_in[4];
    const float* Wk       = (const float*)d_in[5];
    const float* Wv       = (const float*)d_in[6];
    const float* Wout_map = (const float*)d_in[7];
    const float* gQ1      = (const float*)d_in[8];
    const float* gQ2      = (const float*)d_in[9];
    const float* gK1      = (const float*)d_in[10];
    const float* gK2      = (const float*)d_in[11];
    const float* gWa      = (const float*)d_in[12];
    const float* gWg      = (const float*)d_in[13];
    const float* gWout    = (const float*)d_in[14];
    float* out = (float*)d_out;

    // dependency order: k0 -> k1a -> k1bc -> k34 -> k5
    k0<<<1, 256>>>(Wout_map, gWg, gWout, gQ2, gK2, gWa, Wq, Wk);  // idx 0
    k1a<<<BN, 256>>>(Q_in, K_in, out);                            // idx 1
    k1bc<<<BN, 288>>>(V_in, Wv, gQ1, gK1);                        // idx 2
    dim3 g34((NN + 7) / 8, BB);
    k34<<<g34, 288>>>(adj, out);                                  // idx 3  <-- profiled
    k5<<<1480, 256>>>(gWout, out);                                // idx 4
}